// round 1
// baseline (speedup 1.0000x reference)
#include <cuda_runtime.h>
#include <cuda_bf16.h>

// Problem dims (fixed per reference setup_inputs)
#define BB 64
#define TT 1024
#define II 512
#define HH 512
#define MM (BB * TT)   // 65536 rows of the GEMM

#define ALPHA_LO 0.8187307530779818f   // exp(-1/5)
#define ALPHA_HI 0.9607894391523232f   // exp(-1/25)

// 128 MB scratch for Wx = x @ W^T  (device global: allocation-guard safe)
__device__ float g_wx[(size_t)MM * HH];

// ---------------------------------------------------------------------------
// Phase 1: fp32 GEMM  C[m,n] = sum_k x[m,k] * W[n,k]
// Both operands are K-contiguous (row-major [M,K] and [N,K]) -> "NT" gemm.
// 128x128 tile, BK=8, 256 threads, 8x8 microtile per thread.
// ---------------------------------------------------------------------------
__global__ __launch_bounds__(256, 2)
void gemm_nt_f32(const float* __restrict__ A, const float* __restrict__ Bw) {
    __shared__ float As[8][128];
    __shared__ float Bs[8][128];

    const int tid = threadIdx.x;          // 0..255
    const int m0  = blockIdx.y * 128;
    const int n0  = blockIdx.x * 128;
    const int tx  = tid & 15;             // 0..15 -> n microtile
    const int ty  = tid >> 4;             // 0..15 -> m microtile

    // Global load assignment: 128 rows x 8 cols per tile = 256 float4 loads
    const int lr = tid >> 1;              // 0..127 row within tile
    const int lc = (tid & 1) * 4;         // 0 or 4

    const float* Aptr = A  + (size_t)(m0 + lr) * II + lc;
    const float* Bptr = Bw + (size_t)(n0 + lr) * II + lc;

    float acc[8][8];
    #pragma unroll
    for (int i = 0; i < 8; i++)
        #pragma unroll
        for (int j = 0; j < 8; j++) acc[i][j] = 0.0f;

    for (int k0 = 0; k0 < II; k0 += 8) {
        // Fetch next K-slab into registers (overlaps with prior compute)
        const float4 av = *(const float4*)(Aptr + k0);
        const float4 bv = *(const float4*)(Bptr + k0);

        __syncthreads();   // prior compute done before overwriting smem
        As[lc + 0][lr] = av.x; As[lc + 1][lr] = av.y;
        As[lc + 2][lr] = av.z; As[lc + 3][lr] = av.w;
        Bs[lc + 0][lr] = bv.x; Bs[lc + 1][lr] = bv.y;
        Bs[lc + 2][lr] = bv.z; Bs[lc + 3][lr] = bv.w;
        __syncthreads();

        #pragma unroll
        for (int k = 0; k < 8; k++) {
            float ar[8], br[8];
            // vectorized smem reads (float4 x2)
            *(float4*)(&ar[0]) = *(const float4*)(&As[k][ty * 8 + 0]);
            *(float4*)(&ar[4]) = *(const float4*)(&As[k][ty * 8 + 4]);
            *(float4*)(&br[0]) = *(const float4*)(&Bs[k][tx * 8 + 0]);
            *(float4*)(&br[4]) = *(const float4*)(&Bs[k][tx * 8 + 4]);
            #pragma unroll
            for (int i = 0; i < 8; i++)
                #pragma unroll
                for (int j = 0; j < 8; j++)
                    acc[i][j] = fmaf(ar[i], br[j], acc[i][j]);
        }
    }

    // Write C tile (coalesced float4 stores)
    #pragma unroll
    for (int i = 0; i < 8; i++) {
        float* crow = g_wx + (size_t)(m0 + ty * 8 + i) * HH + n0 + tx * 8;
        *(float4*)(crow + 0) = make_float4(acc[i][0], acc[i][1], acc[i][2], acc[i][3]);
        *(float4*)(crow + 4) = make_float4(acc[i][4], acc[i][5], acc[i][6], acc[i][7]);
    }
}

// ---------------------------------------------------------------------------
// Phase 2: LIF scan. One thread per (b,h) lane; T sequential.
// u = al*(u - s) + (1-al)*wx ;  s = (u - 1 > 0)
// Loads batched by 16 for MLP; fully coalesced across h.
// ---------------------------------------------------------------------------
__global__ __launch_bounds__(128)
void lif_scan(const float* __restrict__ alpha,
              const float* __restrict__ u0,
              const float* __restrict__ s0,
              float* __restrict__ out) {
    const int g = blockIdx.x * blockDim.x + threadIdx.x;  // 0..B*H-1
    const int b = g >> 9;      // / 512
    const int h = g & 511;

    float al = alpha[h];
    al = fminf(fmaxf(al, ALPHA_LO), ALPHA_HI);
    const float ial = 1.0f - al;

    float u = u0[g];
    float s = s0[g];

    const float* p = g_wx + (size_t)b * TT * HH + h;
    float*       q = out  + (size_t)b * TT * HH + h;

    #pragma unroll 1
    for (int t = 0; t < TT; t += 16) {
        float w[16];
        #pragma unroll
        for (int j = 0; j < 16; j++)
            w[j] = __ldg(p + (size_t)(t + j) * HH);
        #pragma unroll
        for (int j = 0; j < 16; j++) {
            u = fmaf(al, u - s, ial * w[j]);
            s = (u - 1.0f > 0.0f) ? 1.0f : 0.0f;
            q[(size_t)(t + j) * HH] = s;
        }
    }
}

// ---------------------------------------------------------------------------
extern "C" void kernel_launch(void* const* d_in, const int* in_sizes, int n_in,
                              void* d_out, int out_size) {
    const float* x     = (const float*)d_in[0];  // [B,T,I]
    const float* W     = (const float*)d_in[1];  // [H,I]
    const float* alpha = (const float*)d_in[2];  // [H]
    const float* u0    = (const float*)d_in[3];  // [B,H]
    const float* s0    = (const float*)d_in[4];  // [B,H]
    float* out = (float*)d_out;                  // [B,T,H]

    dim3 ggrid(HH / 128, MM / 128);              // (4, 512)
    gemm_nt_f32<<<ggrid, 256>>>(x, W);

    lif_scan<<<(BB * HH) / 128, 128>>>(alpha, u0, s0, out);
}

// round 3
// speedup vs baseline: 2.1368x; 2.1368x over previous
#include <cuda_runtime.h>
#include <cuda_fp16.h>
#include <cstdint>

#define BB 64
#define TT 1024
#define II 512
#define HH 512
#define MM (BB*TT)              // 65536

#define ALPHA_LO 0.8187307530779818f   // exp(-1/5)
#define ALPHA_HI 0.9607894391523232f   // exp(-1/25)

// Device-global scratch (allocation-guard safe)
__device__ float  g_wx[(size_t)MM * HH];        // 128 MB
__device__ __half g_ah[(size_t)MM * II];        // 64 MB  x high half
__device__ __half g_al[(size_t)MM * II];        // 64 MB  x low  half
__device__ __half g_bh[(size_t)HH * II];        // 512 KB (2048*W) high
__device__ __half g_bl[(size_t)HH * II];        // 512 KB (2048*W) low

// ---------------------------------------------------------------------------
__device__ __forceinline__ uint32_t smem_u32(const void* p) {
    uint32_t a;
    asm("{ .reg .u64 t; cvta.to.shared.u64 t, %1; cvt.u32.u64 %0, t; }" : "=r"(a) : "l"(p));
    return a;
}
__device__ __forceinline__ void cp16(uint32_t dst, const void* src) {
    asm volatile("cp.async.cg.shared.global [%0], [%1], 16;" :: "r"(dst), "l"(src));
}
__device__ __forceinline__ void ldsm_x4(uint32_t* r, uint32_t addr) {
    asm volatile("ldmatrix.sync.aligned.m8n8.x4.shared.b16 {%0,%1,%2,%3}, [%4];"
                 : "=r"(r[0]), "=r"(r[1]), "=r"(r[2]), "=r"(r[3]) : "r"(addr));
}
__device__ __forceinline__ void mma16816(float* c, const uint32_t* a, uint32_t b0, uint32_t b1) {
    asm volatile(
        "mma.sync.aligned.m16n8k16.row.col.f32.f16.f16.f32 "
        "{%0,%1,%2,%3}, {%4,%5,%6,%7}, {%8,%9}, {%0,%1,%2,%3};"
        : "+f"(c[0]), "+f"(c[1]), "+f"(c[2]), "+f"(c[3])
        : "r"(a[0]), "r"(a[1]), "r"(a[2]), "r"(a[3]), "r"(b0), "r"(b1));
}

// ---------------------------------------------------------------------------
// Prep A: split x (fp32) into fp16 high/low halves.  8 elems per thread.
// ---------------------------------------------------------------------------
__global__ __launch_bounds__(256)
void prep_a(const float* __restrict__ x) {
    size_t i = ((size_t)blockIdx.x * 256 + threadIdx.x) * 8;
    float4 v0 = *(const float4*)(x + i);
    float4 v1 = *(const float4*)(x + i + 4);
    float v[8] = {v0.x, v0.y, v0.z, v0.w, v1.x, v1.y, v1.z, v1.w};
    __half h[8], l[8];
    #pragma unroll
    for (int j = 0; j < 8; j++) {
        h[j] = __float2half_rn(v[j]);
        l[j] = __float2half_rn(v[j] - __half2float(h[j]));
    }
    *(uint4*)(g_ah + i) = *(uint4*)h;
    *(uint4*)(g_al + i) = *(uint4*)l;
}

// Prep B: W scaled by 2048, split into fp16 high/low. 4 elems per thread.
__global__ __launch_bounds__(256)
void prep_b(const float* __restrict__ W) {
    size_t i = ((size_t)blockIdx.x * 256 + threadIdx.x) * 4;
    float4 v = *(const float4*)(W + i);
    float s[4] = {v.x * 2048.0f, v.y * 2048.0f, v.z * 2048.0f, v.w * 2048.0f};
    __half h[4], l[4];
    #pragma unroll
    for (int j = 0; j < 4; j++) {
        h[j] = __float2half_rn(s[j]);
        l[j] = __float2half_rn(s[j] - __half2float(h[j]));
    }
    *(uint2*)(g_bh + i) = *(uint2*)h;
    *(uint2*)(g_bl + i) = *(uint2*)l;
}

// ---------------------------------------------------------------------------
// GEMM: Wx[m,n] = (xh.wh' + xh.wl' + xl.wh') / 2048   (w' = 2048 w)
// CTA tile 128x128, BK=32, 8 warps (4m x 2n), warp tile 32x64.
// 48 k-chunks: seg0 (ah,bh) seg1 (ah,bl) seg2 (al,bh), 16 chunks each.
// 4-stage cp.async pipeline; smem stage = A 8KB + B 8KB.
// ---------------------------------------------------------------------------
#define BK 32
#define NST 4
#define STAGE 16384
#define NCHUNK 48

__global__ __launch_bounds__(256, 2)
void gemm_mma(void) {
    extern __shared__ char sm[];
    const uint32_t sbase = smem_u32(sm);
    const int tid  = threadIdx.x;
    const int lane = tid & 31;
    const int warp = tid >> 5;
    const int wm = warp & 3;          // 0..3 -> m offset 32*wm
    const int wn = warp >> 2;         // 0..1 -> n offset 64*wn
    const int m0 = blockIdx.y * 128;
    const int n0 = blockIdx.x * 128;

    // per-thread cp.async assignment (2 chunks per tile): rows r0, r0+64, chunk ch
    const int r0 = tid >> 2;          // 0..63
    const int ch = tid & 3;           // 16B chunk within 64B row
    const int phys = ch ^ ((r0 >> 1) & 3);
    const uint32_t dA0 = (uint32_t)(r0 * 64 + phys * 16);
    const uint32_t dA1 = dA0 + 64 * 64;

    float acc[2][8][4];
    #pragma unroll
    for (int i = 0; i < 2; i++)
        #pragma unroll
        for (int j = 0; j < 8; j++)
            #pragma unroll
            for (int q = 0; q < 4; q++) acc[i][j][q] = 0.0f;

    // ldmatrix source addresses (offsets within a stage)
    // A: row = wm*32 + mi*16 + (lane&15), chunk = kk/8 + (lane>>4)
    // B: row = wn*64 + g*16 + ((lane>>4)<<3) + (lane&7), chunk = kk/8 + ((lane>>3)&1)
    const int arow = wm * 32 + (lane & 15);
    const int ach  = lane >> 4;
    const int brow = wn * 64 + ((lane >> 4) << 3) + (lane & 7);
    const int bch  = (lane >> 3) & 1;

    auto issue = [&](int it) {
        const int s  = it >> 4;        // segment 0,1,2
        const int kc = it & 15;
        const __half* Aseg = (s < 2) ? g_ah : g_al;
        const __half* Bseg = (s == 1) ? g_bl : g_bh;
        const uint32_t stb = sbase + (uint32_t)(it & (NST - 1)) * STAGE;
        const __half* asrc = Aseg + (size_t)(m0 + r0) * II + kc * BK + ch * 8;
        const __half* bsrc = Bseg + (size_t)(n0 + r0) * II + kc * BK + ch * 8;
        cp16(stb + dA0, asrc);
        cp16(stb + dA1, asrc + (size_t)64 * II);
        cp16(stb + 8192 + dA0, bsrc);
        cp16(stb + 8192 + dA1, bsrc + (size_t)64 * II);
        asm volatile("cp.async.commit_group;");
    };

    #pragma unroll
    for (int it = 0; it < NST - 1; it++) issue(it);

    for (int it = 0; it < NCHUNK; it++) {
        asm volatile("cp.async.wait_group %0;" :: "n"(NST - 2));
        __syncthreads();
        if (it + NST - 1 < NCHUNK) issue(it + NST - 1);

        const uint32_t As = sbase + (uint32_t)(it & (NST - 1)) * STAGE;
        const uint32_t Bs = As + 8192;

        #pragma unroll
        for (int kk = 0; kk < 2; kk++) {          // two k16 steps per chunk
            uint32_t a[2][4];
            #pragma unroll
            for (int mi = 0; mi < 2; mi++) {
                int row = arow + mi * 16;
                int c   = kk * 2 + ach;
                ldsm_x4(a[mi], As + row * 64 + (c ^ ((row >> 1) & 3)) * 16);
            }
            uint32_t b[4][4];
            #pragma unroll
            for (int g = 0; g < 4; g++) {
                int row = brow + g * 16;
                int c   = kk * 2 + bch;
                ldsm_x4(b[g], Bs + row * 64 + (c ^ ((row >> 1) & 3)) * 16);
            }
            #pragma unroll
            for (int mi = 0; mi < 2; mi++)
                #pragma unroll
                for (int nj = 0; nj < 8; nj++)
                    mma16816(acc[mi][nj], a[mi], b[nj >> 1][(nj & 1) * 2],
                             b[nj >> 1][(nj & 1) * 2 + 1]);
        }
    }

    // Epilogue: scale by 1/2048, store fp32
    const float inv = 1.0f / 2048.0f;
    #pragma unroll
    for (int mi = 0; mi < 2; mi++) {
        const int r = m0 + wm * 32 + mi * 16 + (lane >> 2);
        #pragma unroll
        for (int nj = 0; nj < 8; nj++) {
            const int c = n0 + wn * 64 + nj * 8 + 2 * (lane & 3);
            float* p0 = g_wx + (size_t)r * HH + c;
            float* p1 = g_wx + (size_t)(r + 8) * HH + c;
            *(float2*)p0 = make_float2(acc[mi][nj][0] * inv, acc[mi][nj][1] * inv);
            *(float2*)p1 = make_float2(acc[mi][nj][2] * inv, acc[mi][nj][3] * inv);
        }
    }
}

// ---------------------------------------------------------------------------
// LIF scan: 1 thread per (b,h), double-buffered prefetch, streaming hints.
// ---------------------------------------------------------------------------
__global__ __launch_bounds__(256)
void lif_scan(const float* __restrict__ alpha,
              const float* __restrict__ u0,
              const float* __restrict__ s0,
              float* __restrict__ out) {
    const int g = blockIdx.x * 256 + threadIdx.x;
    const int b = g >> 9;
    const int h = g & 511;

    float al = alpha[h];
    al = fminf(fmaxf(al, ALPHA_LO), ALPHA_HI);
    const float ial = 1.0f - al;

    float u = u0[g];
    float s = s0[g];

    const float* p = g_wx + (size_t)b * TT * HH + h;
    float*       q = out  + (size_t)b * TT * HH + h;

    float w[2][16];
    #pragma unroll
    for (int j = 0; j < 16; j++) w[0][j] = __ldcs(p + (size_t)j * HH);

    int buf = 0;
    #pragma unroll 1
    for (int t = 0; t < TT; t += 16) {
        if (t + 16 < TT) {
            #pragma unroll
            for (int j = 0; j < 16; j++)
                w[buf ^ 1][j] = __ldcs(p + (size_t)(t + 16 + j) * HH);
        }
        #pragma unroll
        for (int j = 0; j < 16; j++) {
            u = fmaf(al, u - s, ial * w[buf][j]);
            s = (u - 1.0f > 0.0f) ? 1.0f : 0.0f;
            __stcs(q + (size_t)(t + j) * HH, s);
        }
        buf ^= 1;
    }
}

// ---------------------------------------------------------------------------
extern "C" void kernel_launch(void* const* d_in, const int* in_sizes, int n_in,
                              void* d_out, int out_size) {
    const float* x     = (const float*)d_in[0];  // [B,T,I]
    const float* W     = (const float*)d_in[1];  // [H,I]
    const float* alpha = (const float*)d_in[2];  // [H]
    const float* u0    = (const float*)d_in[3];  // [B,H]
    const float* s0    = (const float*)d_in[4];  // [B,H]
    float* out = (float*)d_out;                  // [B,T,H]

    static bool attr_set = false;
    if (!attr_set) {
        cudaFuncSetAttribute(gemm_mma, cudaFuncAttributeMaxDynamicSharedMemorySize,
                             NST * STAGE);
        attr_set = true;
    }

    prep_a<<<(int)(((size_t)MM * II) / 8 / 256), 256>>>(x);
    prep_b<<<(int)(((size_t)HH * II) / 4 / 256), 256>>>(W);

    dim3 grid(HH / 128, MM / 128);               // (4, 512) = 2048 CTAs
    gemm_mma<<<grid, 256, NST * STAGE>>>();

    lif_scan<<<(BB * HH) / 256, 256>>>(alpha, u0, s0, out);
}

// round 4
// speedup vs baseline: 2.1372x; 1.0002x over previous
#include <cuda_runtime.h>
#include <cuda_fp16.h>
#include <cstdint>

#define BB 64
#define TT 1024
#define II 512
#define HH 512
#define MM (BB*TT)              // 65536

#define ALPHA_LO 0.8187307530779818f   // exp(-1/5)
#define ALPHA_HI 0.9607894391523232f   // exp(-1/25)

// Device-global scratch (allocation-guard safe)
__device__ float  g_wx[(size_t)MM * HH];        // 128 MB
__device__ __half g_bh[(size_t)HH * II];        // 512 KB (2048*W) high
__device__ __half g_bl[(size_t)HH * II];        // 512 KB (2048*W) low

// ---------------------------------------------------------------------------
__device__ __forceinline__ uint32_t smem_u32(const void* p) {
    uint32_t a;
    asm("{ .reg .u64 t; cvta.to.shared.u64 t, %1; cvt.u32.u64 %0, t; }" : "=r"(a) : "l"(p));
    return a;
}
__device__ __forceinline__ void cp16(uint32_t dst, const void* src) {
    asm volatile("cp.async.cg.shared.global [%0], [%1], 16;" :: "r"(dst), "l"(src));
}
__device__ __forceinline__ void ldsm_x4(uint32_t* r, uint32_t addr) {
    asm volatile("ldmatrix.sync.aligned.m8n8.x4.shared.b16 {%0,%1,%2,%3}, [%4];"
                 : "=r"(r[0]), "=r"(r[1]), "=r"(r[2]), "=r"(r[3]) : "r"(addr));
}
__device__ __forceinline__ void mma16816(float* c, const uint32_t* a, uint32_t b0, uint32_t b1) {
    asm volatile(
        "mma.sync.aligned.m16n8k16.row.col.f32.f16.f16.f32 "
        "{%0,%1,%2,%3}, {%4,%5,%6,%7}, {%8,%9}, {%0,%1,%2,%3};"
        : "+f"(c[0]), "+f"(c[1]), "+f"(c[2]), "+f"(c[3])
        : "r"(a[0]), "r"(a[1]), "r"(a[2]), "r"(a[3]), "r"(b0), "r"(b1));
}
__device__ __forceinline__ uint32_t h2bits(__half2 h) {
    return *reinterpret_cast<uint32_t*>(&h);
}

// ---------------------------------------------------------------------------
// Prep B: W scaled by 2048, split into fp16 high/low. 4 elems per thread.
// ---------------------------------------------------------------------------
__global__ __launch_bounds__(256)
void prep_b(const float* __restrict__ W) {
    size_t i = ((size_t)blockIdx.x * 256 + threadIdx.x) * 4;
    float4 v = *(const float4*)(W + i);
    float sc[4] = {v.x * 2048.0f, v.y * 2048.0f, v.z * 2048.0f, v.w * 2048.0f};
    __half h[4], l[4];
    #pragma unroll
    for (int j = 0; j < 4; j++) {
        h[j] = __float2half_rn(sc[j]);
        l[j] = __float2half_rn(sc[j] - __half2float(h[j]));
    }
    *(uint2*)(g_bh + i) = *(uint2*)h;
    *(uint2*)(g_bl + i) = *(uint2*)l;
}

// ---------------------------------------------------------------------------
// GEMM: Wx[m,n] = (xh.wh' + xh.wl' + xl.wh') / 2048  (w' = 2048*W)
// CTA tile 128x128, BK=32, 16 k-chunks. A: fp32 global -> registers ->
// hi/lo fp16 MMA fragments (no A smem, no prep_a kernel). B: cp.async
// 3-stage pipeline, ldmatrix. 8 warps (4m x 2n), warp tile 32x64.
// ---------------------------------------------------------------------------
#define NST 3
#define BSTAGE 16384   // bh 8KB + bl 8KB

__global__ __launch_bounds__(256, 2)
void gemm_mma(const float* __restrict__ X) {
    __shared__ char sm[NST * BSTAGE];   // 48 KB static
    const uint32_t sbase = smem_u32(sm);
    const int tid  = threadIdx.x;
    const int lane = tid & 31;
    const int warp = tid >> 5;
    const int wm = warp & 3;
    const int wn = warp >> 2;
    const int m0 = blockIdx.y * 128;
    const int n0 = blockIdx.x * 128;

    // --- B cp.async mapping: 128 threads per matrix (bh/bl), one 64B row each
    const int bsel    = tid >> 7;        // 0 -> bh, 1 -> bl
    const int brow_ld = tid & 127;
    const __half* bsrc = (bsel ? g_bl : g_bh) + (size_t)(n0 + brow_ld) * II;
    const uint32_t bdst = sbase + (uint32_t)bsel * 8192 + (uint32_t)brow_ld * 64;
    const int bxor = (brow_ld >> 1) & 3;

    auto issueB = [&](int it) {
        const uint32_t stb = bdst + (uint32_t)(it % NST) * BSTAGE;
        const __half* s = bsrc + it * 32;
        #pragma unroll
        for (int ch = 0; ch < 4; ch++)
            cp16(stb + (uint32_t)((ch ^ bxor) * 16), s + ch * 8);
        asm volatile("cp.async.commit_group;");
    };

    issueB(0);
    issueB(1);

    // --- A fragment source pointer (per-thread)
    const int r  = lane >> 2;
    const int c2 = (lane & 3) * 2;
    const float* xb = X + (size_t)(m0 + wm * 32 + r) * II + c2;

    // --- B ldmatrix addressing (same mapping as validated R3 kernel)
    const int brow = wn * 64 + ((lane >> 4) << 3) + (lane & 7);
    const int bch  = (lane >> 3) & 1;

    float acc[2][8][4];
    #pragma unroll
    for (int i = 0; i < 2; i++)
        #pragma unroll
        for (int j = 0; j < 8; j++)
            #pragma unroll
            for (int q = 0; q < 4; q++) acc[i][j][q] = 0.0f;

    for (int it = 0; it < 16; it++) {
        asm volatile("cp.async.wait_group %0;" :: "n"(1));
        __syncthreads();
        if (it + 2 < 16) issueB(it + 2);
        else             asm volatile("cp.async.commit_group;");

        const uint32_t stg = sbase + (uint32_t)(it % NST) * BSTAGE;

        #pragma unroll
        for (int kk = 0; kk < 2; kk++) {
            const int koff = it * 32 + kk * 16;

            // A fragments: load fp32, split hi/lo in registers
            uint32_t ah[2][4], al[2][4];
            #pragma unroll
            for (int mi = 0; mi < 2; mi++) {
                #pragma unroll
                for (int j = 0; j < 4; j++) {
                    const float2 f = *(const float2*)(xb + (size_t)(mi * 16 + (j & 1) * 8) * II
                                                      + koff + (j >> 1) * 8);
                    __half2 h  = __float22half2_rn(f);
                    float2  hf = __half22float2(h);
                    __half2 l  = __floats2half2_rn(f.x - hf.x, f.y - hf.y);
                    ah[mi][j] = h2bits(h);
                    al[mi][j] = h2bits(l);
                }
            }

            uint32_t b[4][4];
            // bh: segments (ah.bh) and (al.bh)
            #pragma unroll
            for (int g = 0; g < 4; g++) {
                const int row = brow + g * 16;
                ldsm_x4(b[g], stg + row * 64 + (((kk * 2 + bch) ^ ((row >> 1) & 3)) * 16));
            }
            #pragma unroll
            for (int mi = 0; mi < 2; mi++)
                #pragma unroll
                for (int nj = 0; nj < 8; nj++)
                    mma16816(acc[mi][nj], ah[mi], b[nj >> 1][(nj & 1) * 2],
                             b[nj >> 1][(nj & 1) * 2 + 1]);
            #pragma unroll
            for (int mi = 0; mi < 2; mi++)
                #pragma unroll
                for (int nj = 0; nj < 8; nj++)
                    mma16816(acc[mi][nj], al[mi], b[nj >> 1][(nj & 1) * 2],
                             b[nj >> 1][(nj & 1) * 2 + 1]);
            // bl: segment (ah.bl)
            #pragma unroll
            for (int g = 0; g < 4; g++) {
                const int row = brow + g * 16;
                ldsm_x4(b[g], stg + 8192 + row * 64 + (((kk * 2 + bch) ^ ((row >> 1) & 3)) * 16));
            }
            #pragma unroll
            for (int mi = 0; mi < 2; mi++)
                #pragma unroll
                for (int nj = 0; nj < 8; nj++)
                    mma16816(acc[mi][nj], ah[mi], b[nj >> 1][(nj & 1) * 2],
                             b[nj >> 1][(nj & 1) * 2 + 1]);
        }
    }

    // Epilogue: undo the 2048 scale, store fp32
    const float inv = 1.0f / 2048.0f;
    #pragma unroll
    for (int mi = 0; mi < 2; mi++) {
        const int rr = m0 + wm * 32 + mi * 16 + (lane >> 2);
        #pragma unroll
        for (int nj = 0; nj < 8; nj++) {
            const int cc = n0 + wn * 64 + nj * 8 + 2 * (lane & 3);
            float* p0 = g_wx + (size_t)rr * HH + cc;
            float* p1 = g_wx + (size_t)(rr + 8) * HH + cc;
            *(float2*)p0 = make_float2(acc[mi][nj][0] * inv, acc[mi][nj][1] * inv);
            *(float2*)p1 = make_float2(acc[mi][nj][2] * inv, acc[mi][nj][3] * inv);
        }
    }
}

// ---------------------------------------------------------------------------
// LIF scan: 1 thread per (b,h). STATIC double-buffer (no local-mem demotion),
// 256 blocks x 128 threads so all 148 SMs are busy.
// ---------------------------------------------------------------------------
__global__ __launch_bounds__(128)
void lif_scan(const float* __restrict__ alpha,
              const float* __restrict__ u0,
              const float* __restrict__ s0,
              float* __restrict__ out) {
    const int g = blockIdx.x * 128 + threadIdx.x;
    const int b = g >> 9;
    const int h = g & 511;

    float al = alpha[h];
    al = fminf(fmaxf(al, ALPHA_LO), ALPHA_HI);
    const float ial = 1.0f - al;

    float u = u0[g];
    float s = s0[g];

    const float* p = g_wx + (size_t)b * TT * HH + h;
    float*       q = out  + (size_t)b * TT * HH + h;

    float wA[16], wB[16];
    #pragma unroll
    for (int j = 0; j < 16; j++) wA[j] = __ldg(p + (size_t)j * HH);

    #pragma unroll 1
    for (int t = 0; t < TT; t += 32) {
        #pragma unroll
        for (int j = 0; j < 16; j++) wB[j] = __ldg(p + (size_t)(t + 16 + j) * HH);
        #pragma unroll
        for (int j = 0; j < 16; j++) {
            u = fmaf(al, u - s, ial * wA[j]);
            s = (u - 1.0f > 0.0f) ? 1.0f : 0.0f;
            q[(size_t)(t + j) * HH] = s;
        }
        if (t + 32 < TT) {
            #pragma unroll
            for (int j = 0; j < 16; j++) wA[j] = __ldg(p + (size_t)(t + 32 + j) * HH);
        }
        #pragma unroll
        for (int j = 0; j < 16; j++) {
            u = fmaf(al, u - s, ial * wB[j]);
            s = (u - 1.0f > 0.0f) ? 1.0f : 0.0f;
            q[(size_t)(t + 16 + j) * HH] = s;
        }
    }
}

// ---------------------------------------------------------------------------
extern "C" void kernel_launch(void* const* d_in, const int* in_sizes, int n_in,
                              void* d_out, int out_size) {
    const float* x     = (const float*)d_in[0];  // [B,T,I]
    const float* W     = (const float*)d_in[1];  // [H,I]
    const float* alpha = (const float*)d_in[2];  // [H]
    const float* u0    = (const float*)d_in[3];  // [B,H]
    const float* s0    = (const float*)d_in[4];  // [B,H]
    float* out = (float*)d_out;                  // [B,T,H]

    prep_b<<<(int)(((size_t)HH * II) / 4 / 256), 256>>>(W);

    dim3 grid(HH / 128, MM / 128);               // (4, 512) = 2048 CTAs
    gemm_mma<<<grid, 256>>>(x);

    lif_scan<<<(BB * HH) / 128, 128>>>(alpha, u0, s0, out);
}